// round 17
// baseline (speedup 1.0000x reference)
#include <cuda_runtime.h>
#include <cuda_fp16.h>
#include <cstdint>
#include <cstring>

#define T 24
#define D 64
#define KW 3
#define KDIM 192
#define RPC 8              // r-rows per CTA
#define MROWS (RPC * T)    // 192 output rows per CTA (exact: grid*192 == Mtot)
#define BLOCK 384          // 12 warps: 6 m-tiles (32) x 2 n-tiles (32)
#define PITCH 384          // dense row pitch; conflicts avoided by XOR chunk swizzle

// smem: A(192*384=73728) + W(24576) = 98304 -> 2 CTAs/SM
#define OFF_A 0
#define OFF_W 73728
#define SMEM_TOTAL 98304

// chunk swizzle: 16B-chunk c (0..23), row j
#define SWZC(c, j) (((c) & ~7) | (((c) & 7) ^ ((j) & 7)))

// Prepacked folded weights: fp16, dense-swizzled smem image
__device__ unsigned char g_W[64 * PITCH];
__device__ float g_c[D];

__device__ __forceinline__ uint32_t smem_u32(const void* p) {
    uint32_t a;
    asm("{ .reg .u64 t; cvta.to.shared.u64 t, %1; cvt.u32.u64 %0, t; }" : "=r"(a) : "l"(p));
    return a;
}
__device__ __forceinline__ void ldm4(uint32_t* r, uint32_t addr) {
    asm volatile("ldmatrix.sync.aligned.m8n8.x4.shared.b16 {%0,%1,%2,%3}, [%4];"
                 : "=r"(r[0]), "=r"(r[1]), "=r"(r[2]), "=r"(r[3]) : "r"(addr));
}
__device__ __forceinline__ void mma16816(float* c, const uint32_t* a, uint32_t b0, uint32_t b1) {
    asm volatile("mma.sync.aligned.m16n8k16.row.col.f32.f16.f16.f32 "
                 "{%0,%1,%2,%3}, {%4,%5,%6,%7}, {%8,%9}, {%0,%1,%2,%3};"
                 : "+f"(c[0]), "+f"(c[1]), "+f"(c[2]), "+f"(c[3])
                 : "r"(a[0]), "r"(a[1]), "r"(a[2]), "r"(a[3]), "r"(b0), "r"(b1));
}
__device__ __forceinline__ uint32_t bits_h2(__half2 h) {
    uint32_t u; memcpy(&u, &h, 4); return u;
}

// ---------------- prep: fold linear into conv, fp16, swizzled pack ----------------
__global__ void prep_kernel(const float* __restrict__ W_conv,
                            const float* __restrict__ b_conv,
                            const float* __restrict__ W_lin) {
    int gid = blockIdx.x * blockDim.x + threadIdx.x;
    if (gid < D * KDIM) {
        int o2 = gid / KDIM;
        int kk = gid % KDIM;
        int k = kk / D, i = kk % D;
        float s = 0.f;
#pragma unroll 8
        for (int o = 0; o < D; ++o)
            s += W_lin[o2 * D + o] * W_conv[o * (D * KW) + i * KW + k];
        int c = kk >> 3;
        int off = o2 * PITCH + SWZC(c, o2) * 16 + (kk & 7) * 2;
        *(__half*)(g_W + off) = __float2half_rn(s);
    }
    if (gid < D) {
        float s = 0.f;
#pragma unroll 8
        for (int o = 0; o < D; ++o) s += W_lin[gid * D + o] * b_conv[o];
        g_c[gid] = s;
    }
}

// ---------------- main kernel ----------------
__global__ __launch_bounds__(BLOCK, 2)
void temporal_agg_mma(const float* __restrict__ val,
                      const float* __restrict__ b_lin,
                      float* __restrict__ out,
                      int Mtot) {
    extern __shared__ char sm[];
    const uint32_t smb = smem_u32(sm);
    const int tid  = threadIdx.x;
    const int warp = tid >> 5;
    const int lane = tid & 31;
    const int base = blockIdx.x * MROWS;
    const int r0   = blockIdx.x * RPC;

    // copy prepacked weights (L2-resident): 1536 x 16B
    {
        const uint4* gw = (const uint4*)g_W;
        for (int p = tid; p < 64 * PITCH / 16; p += BLOCK)
            *(uint4*)(sm + OFF_W + p * 16) = __ldg(gw + p);
    }

    // ---- rolling-window W3 staging ----
    // Abs[tp,k] = W3[tp+k-1] (zero-padded band sum), except:
    //   Abs[0,2]  = W3[1]  - val[0]   (c==1 override on the k=2 slot)
    //   Abs[23,0] = W3[22] - val[23]  (c==22 override on the k=0 slot)
    // Thread map: 128 groups (rr x ib) x 3 subs; sub owns contiguous c range.
    {
        const int g   = tid / 3;          // 0..127
        const int sub = tid - g * 3;      // 0..2
        const int rr  = g >> 4;           // 0..7
        const int ib  = g & 15;           // 0..15 (float4 channel block)
        const int cs  = sub * 9 - 1;      // -1 / 8 / 17
        const int ce  = (sub == 2) ? 24 : cs + 8;
        const int ckb  = ib >> 1;
        const int hoff = (ib & 1) * 8;
        const int jb0  = rr * T;
        const float* vb = val + ((size_t)(r0 + rr) * T) * D + ib * 4;
        const float4 z = make_float4(0.f, 0.f, 0.f, 0.f);
        float4 vm = (cs >= 1) ? __ldg((const float4*)(vb + (size_t)(cs - 1) * D)) : z;
        float4 v0 = (cs >= 0) ? __ldg((const float4*)(vb + (size_t)cs * D)) : z;
#pragma unroll 3
        for (int c = cs; c <= ce; ++c) {
            float4 vp = (c + 1 < T) ? __ldg((const float4*)(vb + (size_t)(c + 1) * D)) : z;
            float4 w3 = make_float4(vm.x + v0.x + vp.x, vm.y + v0.y + vp.y,
                                    vm.z + v0.z + vp.z, vm.w + v0.w + vp.w);
            // k=0 slot: j = c+1 (c in [-1,22]); edge override at c==22
            if (c <= T - 2) {
                float4 w = w3;
                if (c == T - 2) { w.x -= vp.x; w.y -= vp.y; w.z -= vp.z; w.w -= vp.w; }
                const int j = jb0 + c + 1;
                *(uint2*)(sm + OFF_A + j * PITCH + SWZC(ckb, j) * 16 + hoff) =
                    make_uint2(bits_h2(__float22half2_rn(make_float2(w.x, w.y))),
                               bits_h2(__float22half2_rn(make_float2(w.z, w.w))));
            }
            // k=1 slot: j = c (c in [0,23])
            if (c >= 0 && c < T) {
                const int j = jb0 + c;
                *(uint2*)(sm + OFF_A + j * PITCH + SWZC(8 + ckb, j) * 16 + hoff) =
                    make_uint2(bits_h2(__float22half2_rn(make_float2(w3.x, w3.y))),
                               bits_h2(__float22half2_rn(make_float2(w3.z, w3.w))));
            }
            // k=2 slot: j = c-1 (c in [1,24]); edge override at c==1
            if (c >= 1) {
                float4 w = w3;
                if (c == 1) { w.x -= vm.x; w.y -= vm.y; w.z -= vm.z; w.w -= vm.w; }
                const int j = jb0 + c - 1;
                *(uint2*)(sm + OFF_A + j * PITCH + SWZC(16 + ckb, j) * 16 + hoff) =
                    make_uint2(bits_h2(__float22half2_rn(make_float2(w.x, w.y))),
                               bits_h2(__float22half2_rn(make_float2(w.z, w.w))));
            }
            vm = v0; v0 = vp;
        }
    }
    __syncthreads();

    // ---------------- mainloop: single fp16 pass, warp tile 32x32 (6m x 2n warp grid) ----------------
    float acc[2][4][4];
#pragma unroll
    for (int mt = 0; mt < 2; ++mt)
#pragma unroll
        for (int nt = 0; nt < 4; ++nt)
#pragma unroll
            for (int q = 0; q < 4; ++q) acc[mt][nt][q] = 0.f;

    const int m0 = (warp >> 1) * 32;
    const int n0 = (warp & 1) * 32;
    const int ja  = m0 + (lane & 15);            // A row for this lane
    const int ahc = (lane >> 4);                 // A chunk parity (k-halves)
    const int jb  = n0 + (lane & 7) + ((lane >> 4) << 3);   // B row
    const int bhc = ((lane >> 3) & 1);           // B chunk parity
    const int jax = ja & 7, jbx = jb & 7;        // rows +16 keep low 3 bits

    const uint32_t aRow  = smb + OFF_A + ja * PITCH;
    const uint32_t aRow2 = aRow + 16 * PITCH;
    const uint32_t bRow  = smb + OFF_W + jb * PITCH;
    const uint32_t bRow2 = bRow + 16 * PITCH;

#pragma unroll
    for (int ks = 0; ks < 12; ++ks) {
        const int ca = ks * 2 + ahc;
        const int cb = ks * 2 + bhc;
        uint32_t a0[4], a1[4], b0[4], b1[4];
        ldm4(a0, aRow  + SWZC(ca, jax) * 16);
        ldm4(a1, aRow2 + SWZC(ca, jax) * 16);
        ldm4(b0, bRow  + SWZC(cb, jbx) * 16);
        ldm4(b1, bRow2 + SWZC(cb, jbx) * 16);
        mma16816(acc[0][0], a0, b0[0], b0[1]);
        mma16816(acc[0][1], a0, b0[2], b0[3]);
        mma16816(acc[0][2], a0, b1[0], b1[1]);
        mma16816(acc[0][3], a0, b1[2], b1[3]);
        mma16816(acc[1][0], a1, b0[0], b0[1]);
        mma16816(acc[1][1], a1, b0[2], b0[3]);
        mma16816(acc[1][2], a1, b1[0], b1[1]);
        mma16816(acc[1][3], a1, b1[2], b1[3]);
    }

    // ---------------- fused epilogue: bias + relu, straight to gmem ----------------
    {
        const int rrow = lane >> 2;
        const int rcol = 2 * (lane & 3);
#pragma unroll
        for (int nt = 0; nt < 4; ++nt) {
            const int col = n0 + nt * 8 + rcol;
            const float2 cc = *(const float2*)(g_c + col);
            const float2 bl = __ldg((const float2*)(b_lin + col));
#pragma unroll
            for (int mt = 0; mt < 2; ++mt)
#pragma unroll
                for (int half = 0; half < 2; ++half) {
                    const int mg = base + m0 + mt * 16 + rrow + half * 8;
                    const int tp = mg % T;
                    const float nb = 3.f - (tp == 0) - (tp == T - 1);
                    const float* a = acc[mt][nt] + half * 2;
                    float2 o;
                    o.x = fmaxf(fmaf(nb, cc.x, bl.x) + a[0], 0.f);
                    o.y = fmaxf(fmaf(nb, cc.y, bl.y) + a[1], 0.f);
                    *(float2*)(out + (size_t)mg * D + col) = o;
                }
        }
    }
}

extern "C" void kernel_launch(void* const* d_in, const int* in_sizes, int n_in,
                              void* d_out, int out_size) {
    const float* value  = (const float*)d_in[0];
    const float* W_conv = (const float*)d_in[1];
    const float* b_conv = (const float*)d_in[2];
    const float* W_lin  = (const float*)d_in[3];
    const float* b_lin  = (const float*)d_in[4];
    float* out = (float*)d_out;

    cudaFuncSetAttribute(temporal_agg_mma, cudaFuncAttributeMaxDynamicSharedMemorySize, SMEM_TOTAL);

    const int rows_total = in_sizes[0] / (T * D);   // 16384
    const int Mtot = rows_total * T;                // 393216

    prep_kernel<<<(D * KDIM + 255) / 256, 256>>>(W_conv, b_conv, W_lin);

    const int grid = rows_total / RPC;              // 2048 (exact)
    temporal_agg_mma<<<grid, BLOCK, SMEM_TOTAL>>>(value, b_lin, out, Mtot);
}